// round 3
// baseline (speedup 1.0000x reference)
#include <cuda_runtime.h>

#define BATCH   64
#define BLKS_PER_IMG 16
#define NBLK    (BATCH * BLKS_PER_IMG)   // 1024
#define TPB     256
#define PW      127
#define PH      127
#define NPATCH  (PH * PW)                // 16129

// per-block partial monomial sums: [block][8]
// 0:Sca0  1:Sca1  2:Scc  3:Sss  4:La0  5:La1  6:La2  7:La3
__device__ float4 g_part[NBLK][2];
__device__ unsigned int g_count = 0;

__global__ void __launch_bounds__(TPB) fused_kernel(
    const float* __restrict__ x,
    const float* __restrict__ conv_w,
    const float* __restrict__ conv_b,
    const float* __restrict__ ry,      // (2,4)
    const float* __restrict__ head_w,  // (1,2)
    const float* __restrict__ head_b,
    float* __restrict__ out)
{
    __shared__ float sh[8][8];
    __shared__ bool  s_last;

    const int tid  = threadIdx.x;
    const int wid  = tid >> 5;
    const int lane = tid & 31;
    const int b    = blockIdx.x >> 4;        // image
    const int k    = blockIdx.x & 15;        // row-group
    const int row  = k * 8 + wid;            // 0..127; 127 invalid

    // Warm L2 with params so the finalizing block's tail loads are cheap.
    if (tid == 0) {
        asm volatile("prefetch.global.L2 [%0];" :: "l"(ry));
        asm volatile("prefetch.global.L2 [%0];" :: "l"(conv_w));
        asm volatile("prefetch.global.L2 [%0];" :: "l"(conv_b));
        asm volatile("prefetch.global.L2 [%0];" :: "l"(head_w));
        asm volatile("prefetch.global.L2 [%0];" :: "l"(head_b));
    }

    float S0 = 0.f, S1 = 0.f, S2 = 0.f, S3 = 0.f;
    float S4 = 0.f, S5 = 0.f, S6 = 0.f, S7 = 0.f;

    if (row < 127) {   // warp-uniform branch
        const float* p = x + (size_t)b * 16384 + row * 128 + lane * 4;
        const float4 v0 = *(const float4*)p;          // row r,   cols 4l..4l+3
        const float4 v1 = *(const float4*)(p + 128);  // row r+1, cols 4l..4l+3

        float ca0, sa0, ca1, sa1, ca2, sa2, ca3, sa3;
        __sincosf(v0.x, &sa0, &ca0);
        __sincosf(v0.y, &sa1, &ca1);
        __sincosf(v0.z, &sa2, &ca2);
        __sincosf(v0.w, &sa3, &ca3);
        // neighbor lane's first-pixel trig (for the c=4l+3 patch)
        const float ca4 = __shfl_down_sync(0xFFFFFFFFu, ca0, 1);
        const float sa4 = __shfl_down_sync(0xFFFFFFFFu, sa0, 1);

        const bool l31 = (lane == 31);
        const bool l0  = (lane == 0);

        const float tc = (ca0 + ca1) + (ca2 + ca3);
        const float ta = (v0.x + v0.y) + (v0.z + v0.w);
        const float tb = (v1.x + v1.y) + (v1.z + v1.w);

        S0 = tc - (l31 ? ca3  : 0.f);   // sum cos(a0), cols 0..126
        S1 = tc - (l0  ? ca0  : 0.f);   // sum cos(a1), cols 1..127
        S2 = ca0 * ca1 + ca1 * ca2 + ca2 * ca3 + (l31 ? 0.f : ca3 * ca4);
        S3 = sa0 * sa1 + sa1 * sa2 + sa2 * sa3 + (l31 ? 0.f : sa3 * sa4);
        S4 = ta - (l31 ? v0.w : 0.f);   // sum a0
        S5 = ta - (l0  ? v0.x : 0.f);   // sum a1
        S6 = tb - (l31 ? v1.w : 0.f);   // sum a2
        S7 = tb - (l0  ? v1.x : 0.f);   // sum a3
    }

    // warp tree reduction (deterministic)
    #pragma unroll
    for (int off = 16; off > 0; off >>= 1) {
        const unsigned m = 0xFFFFFFFFu;
        S0 += __shfl_down_sync(m, S0, off);
        S1 += __shfl_down_sync(m, S1, off);
        S2 += __shfl_down_sync(m, S2, off);
        S3 += __shfl_down_sync(m, S3, off);
        S4 += __shfl_down_sync(m, S4, off);
        S5 += __shfl_down_sync(m, S5, off);
        S6 += __shfl_down_sync(m, S6, off);
        S7 += __shfl_down_sync(m, S7, off);
    }
    if (lane == 0) {
        sh[wid][0] = S0; sh[wid][1] = S1; sh[wid][2] = S2; sh[wid][3] = S3;
        sh[wid][4] = S4; sh[wid][5] = S5; sh[wid][6] = S6; sh[wid][7] = S7;
    }
    __syncthreads();

    // cross-warp reduce (fixed order), funnel to thread 0
    if (tid < 8) {
        float v = sh[0][tid];
        #pragma unroll
        for (int w = 1; w < 8; w++) v += sh[w][tid];
        sh[0][tid] = v;
    }
    __syncthreads();

    if (tid == 0) {
        float4 a = make_float4(sh[0][0], sh[0][1], sh[0][2], sh[0][3]);
        float4 c = make_float4(sh[0][4], sh[0][5], sh[0][6], sh[0][7]);
        g_part[blockIdx.x][0] = a;
        g_part[blockIdx.x][1] = c;
        __threadfence();
        unsigned done = atomicAdd(&g_count, 1u);
        s_last = (done == NBLK - 1);
    }
    __syncthreads();

    // ---- finalizing block: reduce partials, compute coefficients, write out ----
    if (s_last) {
        if (tid < BATCH) {
            const int bb = tid;
            float m0 = 0.f, m1 = 0.f, m2 = 0.f, m3 = 0.f;
            float m4 = 0.f, m5 = 0.f, m6 = 0.f, m7 = 0.f;
            #pragma unroll
            for (int kk = 0; kk < BLKS_PER_IMG; kk++) {
                const float4 pa = __ldcg(&g_part[bb * BLKS_PER_IMG + kk][0]);
                const float4 pc = __ldcg(&g_part[bb * BLKS_PER_IMG + kk][1]);
                m0 += pa.x; m1 += pa.y; m2 += pa.z; m3 += pa.w;
                m4 += pc.x; m5 += pc.y; m6 += pc.z; m7 += pc.w;
            }

            // coefficients (redundant per thread, identical FMA sequence)
            float U[4][4] = {{1,0,0,0},{0,1,0,0},{0,0,1,0},{0,0,0,1}};
            #pragma unroll
            for (int l = 0; l < 2; l++) {
                float c0, s0, c1, s1;
                __sincosf(0.5f * ry[l * 4 + 0], &s0, &c0);
                __sincosf(0.5f * ry[l * 4 + 1], &s1, &c1);
                float A2[2][2]  = {{c0, -s0}, {s0, c0}};
                float B2[2][2]  = {{c1, -s1}, {s1, c1}};
                float T[4][4];
                #pragma unroll
                for (int i = 0; i < 4; i++)
                    #pragma unroll
                    for (int j = 0; j < 4; j++) {
                        float s = 0.f;
                        #pragma unroll
                        for (int kx = 0; kx < 4; kx++)
                            s += A2[i >> 1][kx >> 1] * B2[i & 1][kx & 1] * U[kx][j];
                        T[i][j] = s;
                    }
                #pragma unroll
                for (int j = 0; j < 4; j++) {
                    U[0][j] = T[0][j]; U[1][j] = T[1][j];
                    U[2][j] = T[3][j]; U[3][j] = T[2][j];
                }
            }
            float M00 = 0, M03 = 0, M33 = 0, M11 = 0, M12 = 0, M22 = 0;
            #pragma unroll
            for (int i = 0; i < 4; i++) {
                float z = (i < 2) ? 1.0f : -1.0f;
                M00 += z * U[i][0] * U[i][0];
                M03 += z * U[i][0] * U[i][3];
                M33 += z * U[i][3] * U[i][3];
                M11 += z * U[i][1] * U[i][1];
                M12 += z * U[i][1] * U[i][2];
                M22 += z * U[i][2] * U[i][2];
            }
            const float hw0 = head_w[0];
            const float hw1 = head_w[1];
            const float q0 = hw1 * M00;
            const float q1 = hw1 * (-2.0f * M03);
            const float q2 = hw1 * M33;
            const float q3 = hw1 * M11;
            const float q4 = hw1 * (2.0f * M12);
            const float q5 = hw1 * M22;
            // half-angle basis coefficients
            const float A = 0.25f * (q0 + q2 + q3 + q5);
            const float Bc = 0.25f * (q0 - q2 + q3 - q5);   // * Sum cos a0
            const float Cc = 0.25f * (q0 - q2 - q3 + q5);   // * Sum cos a1
            const float Dc = 0.25f * (q0 + q2 - q3 - q5);   // * Sum ca0*ca1
            const float Ec = 0.25f * (q1 + q4);             // * Sum sa0*sa1

            const float qsum = A * (float)NPATCH + Bc * m0 + Cc * m1 + Dc * m2 + Ec * m3;
            const float csum = hw0 * (conv_w[0] * m4 + conv_w[1] * m5 +
                                      conv_w[2] * m6 + conv_w[3] * m7);
            out[bb] = (qsum + csum) * (1.0f / (float)NPATCH)
                      + hw0 * conv_b[0] + head_b[0];
        }
        __syncthreads();
        if (tid == 0) g_count = 0;   // reset for next graph replay
    }
}

extern "C" void kernel_launch(void* const* d_in, const int* in_sizes, int n_in,
                              void* d_out, int out_size) {
    const float* x      = (const float*)d_in[0];
    const float* conv_w = (const float*)d_in[1];
    const float* conv_b = (const float*)d_in[2];
    const float* ry     = (const float*)d_in[3];
    const float* head_w = (const float*)d_in[4];
    const float* head_b = (const float*)d_in[5];
    float* out = (float*)d_out;

    fused_kernel<<<NBLK, TPB>>>(x, conv_w, conv_b, ry, head_w, head_b, out);
}

// round 4
// speedup vs baseline: 1.2316x; 1.2316x over previous
#include <cuda_runtime.h>

#define BATCH        64
#define BLKS_PER_IMG 4
#define NBLK         (BATCH * BLKS_PER_IMG)   // 256
#define TPB          256
#define NPATCH       (127 * 127)              // 16129

// per-block partial monomial sums:
// [0]: Sca0, Sca1, Scc, Sss   [1]: La0, La1, La2, La3
__device__ float4       g_part[NBLK][2];
__device__ unsigned int g_cnt[BATCH];   // zero-initialized; finisher resets

__global__ void __launch_bounds__(TPB) fused_kernel(
    const float* __restrict__ x,
    const float* __restrict__ conv_w,
    const float* __restrict__ conv_b,
    const float* __restrict__ ry,      // (2,4)
    const float* __restrict__ head_w,  // (1,2)
    const float* __restrict__ head_b,
    float* __restrict__ out)
{
    __shared__ float sh[8][8];
    __shared__ bool  s_fin;

    const int tid  = threadIdx.x;
    const int wid  = tid >> 5;
    const int lane = tid & 31;
    const int b    = blockIdx.x >> 2;        // image
    const int q    = blockIdx.x & 3;         // quarter (32 rows)

    // Prefetch params into registers early (warp 0): ready long before finalize.
    float pr[8], pw[4], pcb, ph0, ph1, phb;
    if (wid == 0) {
        #pragma unroll
        for (int i = 0; i < 8; i++) pr[i] = ry[i];
        #pragma unroll
        for (int i = 0; i < 4; i++) pw[i] = conv_w[i];
        pcb = conv_b[0]; ph0 = head_w[0]; ph1 = head_w[1]; phb = head_b[0];
    }

    float S0 = 0.f, S1 = 0.f, S2 = 0.f, S3 = 0.f;
    float S4 = 0.f, S5 = 0.f, S6 = 0.f, S7 = 0.f;

    const float* __restrict__ img = x + (size_t)b * 16384;
    const int rbase = q * 32 + wid;

    #pragma unroll
    for (int it = 0; it < 4; it++) {
        const int row = rbase + it * 8;       // v0 row
        if (row < 127) {                      // warp-uniform (only 127 skipped)
            const float* p = img + row * 128 + lane * 4;
            const float4 v0 = *(const float4*)p;
            const float4 v1 = *(const float4*)(p + 128);

            float ca0, sa0, ca1, sa1, ca2, sa2, ca3, sa3;
            __sincosf(v0.x, &sa0, &ca0);
            __sincosf(v0.y, &sa1, &ca1);
            __sincosf(v0.z, &sa2, &ca2);
            __sincosf(v0.w, &sa3, &ca3);
            const float ca4 = __shfl_down_sync(0xFFFFFFFFu, ca0, 1);
            const float sa4 = __shfl_down_sync(0xFFFFFFFFu, sa0, 1);

            const bool l31 = (lane == 31);
            const bool l0  = (lane == 0);

            const float tc = (ca0 + ca1) + (ca2 + ca3);
            const float ta = (v0.x + v0.y) + (v0.z + v0.w);
            const float tb = (v1.x + v1.y) + (v1.z + v1.w);

            S0 += tc - (l31 ? ca3  : 0.f);
            S1 += tc - (l0  ? ca0  : 0.f);
            S2 += ca0 * ca1 + ca1 * ca2 + ca2 * ca3 + (l31 ? 0.f : ca3 * ca4);
            S3 += sa0 * sa1 + sa1 * sa2 + sa2 * sa3 + (l31 ? 0.f : sa3 * sa4);
            S4 += ta - (l31 ? v0.w : 0.f);
            S5 += ta - (l0  ? v0.x : 0.f);
            S6 += tb - (l31 ? v1.w : 0.f);
            S7 += tb - (l0  ? v1.x : 0.f);
        }
    }

    // warp tree reduction (deterministic)
    #pragma unroll
    for (int off = 16; off > 0; off >>= 1) {
        const unsigned m = 0xFFFFFFFFu;
        S0 += __shfl_down_sync(m, S0, off);
        S1 += __shfl_down_sync(m, S1, off);
        S2 += __shfl_down_sync(m, S2, off);
        S3 += __shfl_down_sync(m, S3, off);
        S4 += __shfl_down_sync(m, S4, off);
        S5 += __shfl_down_sync(m, S5, off);
        S6 += __shfl_down_sync(m, S6, off);
        S7 += __shfl_down_sync(m, S7, off);
    }
    if (lane == 0) {
        sh[wid][0] = S0; sh[wid][1] = S1; sh[wid][2] = S2; sh[wid][3] = S3;
        sh[wid][4] = S4; sh[wid][5] = S5; sh[wid][6] = S6; sh[wid][7] = S7;
    }
    __syncthreads();

    if (tid < 8) {   // fixed-order cross-warp reduce
        float v = sh[0][tid];
        #pragma unroll
        for (int w = 1; w < 8; w++) v += sh[w][tid];
        sh[0][tid] = v;
    }
    __syncthreads();

    if (tid == 0) {
        g_part[blockIdx.x][0] = make_float4(sh[0][0], sh[0][1], sh[0][2], sh[0][3]);
        g_part[blockIdx.x][1] = make_float4(sh[0][4], sh[0][5], sh[0][6], sh[0][7]);
        __threadfence();
        unsigned done = atomicAdd(&g_cnt[b], 1u);
        s_fin = (done == BLKS_PER_IMG - 1);
    }
    __syncthreads();

    // ---- per-image finisher: 4th block of this image ----
    if (s_fin && tid == 0) {
        __threadfence();
        float m0 = 0.f, m1 = 0.f, m2 = 0.f, m3 = 0.f;
        float m4 = 0.f, m5 = 0.f, m6 = 0.f, m7 = 0.f;
        #pragma unroll
        for (int k = 0; k < BLKS_PER_IMG; k++) {
            const float4 pa = __ldcg(&g_part[b * BLKS_PER_IMG + k][0]);
            const float4 pc = __ldcg(&g_part[b * BLKS_PER_IMG + k][1]);
            m0 += pa.x; m1 += pa.y; m2 += pa.z; m3 += pa.w;
            m4 += pc.x; m5 += pc.y; m6 += pc.z; m7 += pc.w;
        }

        // coefficients from prefetched params (registers)
        float U[4][4] = {{1,0,0,0},{0,1,0,0},{0,0,1,0},{0,0,0,1}};
        #pragma unroll
        for (int l = 0; l < 2; l++) {
            float c0, s0, c1, s1;
            __sincosf(0.5f * pr[l * 4 + 0], &s0, &c0);
            __sincosf(0.5f * pr[l * 4 + 1], &s1, &c1);
            float A2[2][2] = {{c0, -s0}, {s0, c0}};
            float B2[2][2] = {{c1, -s1}, {s1, c1}};
            float T[4][4];
            #pragma unroll
            for (int i = 0; i < 4; i++)
                #pragma unroll
                for (int j = 0; j < 4; j++) {
                    float s = 0.f;
                    #pragma unroll
                    for (int kx = 0; kx < 4; kx++)
                        s += A2[i >> 1][kx >> 1] * B2[i & 1][kx & 1] * U[kx][j];
                    T[i][j] = s;
                }
            #pragma unroll
            for (int j = 0; j < 4; j++) {
                U[0][j] = T[0][j]; U[1][j] = T[1][j];
                U[2][j] = T[3][j]; U[3][j] = T[2][j];
            }
        }
        float M00 = 0, M03 = 0, M33 = 0, M11 = 0, M12 = 0, M22 = 0;
        #pragma unroll
        for (int i = 0; i < 4; i++) {
            float z = (i < 2) ? 1.0f : -1.0f;
            M00 += z * U[i][0] * U[i][0];
            M03 += z * U[i][0] * U[i][3];
            M33 += z * U[i][3] * U[i][3];
            M11 += z * U[i][1] * U[i][1];
            M12 += z * U[i][1] * U[i][2];
            M22 += z * U[i][2] * U[i][2];
        }
        const float c_q0 = ph1 * M00;
        const float c_q1 = ph1 * (-2.0f * M03);
        const float c_q2 = ph1 * M33;
        const float c_q3 = ph1 * M11;
        const float c_q4 = ph1 * (2.0f * M12);
        const float c_q5 = ph1 * M22;
        const float A  = 0.25f * (c_q0 + c_q2 + c_q3 + c_q5);
        const float Bc = 0.25f * (c_q0 - c_q2 + c_q3 - c_q5);
        const float Cc = 0.25f * (c_q0 - c_q2 - c_q3 + c_q5);
        const float Dc = 0.25f * (c_q0 + c_q2 - c_q3 - c_q5);
        const float Ec = 0.25f * (c_q1 + c_q4);

        const float qsum = A * (float)NPATCH + Bc * m0 + Cc * m1 + Dc * m2 + Ec * m3;
        const float csum = ph0 * (pw[0] * m4 + pw[1] * m5 + pw[2] * m6 + pw[3] * m7);
        out[b] = (qsum + csum) * (1.0f / (float)NPATCH) + ph0 * pcb + phb;

        g_cnt[b] = 0;   // reset for next graph replay (4th arrival owns it)
    }
}

extern "C" void kernel_launch(void* const* d_in, const int* in_sizes, int n_in,
                              void* d_out, int out_size) {
    const float* x      = (const float*)d_in[0];
    const float* conv_w = (const float*)d_in[1];
    const float* conv_b = (const float*)d_in[2];
    const float* ry     = (const float*)d_in[3];
    const float* head_w = (const float*)d_in[4];
    const float* head_b = (const float*)d_in[5];
    float* out = (float*)d_out;

    fused_kernel<<<NBLK, TPB>>>(x, conv_w, conv_b, ry, head_w, head_b, out);
}

// round 5
// speedup vs baseline: 1.2362x; 1.0037x over previous
#include <cuda_runtime.h>

#define BATCH        64
#define BLKS_PER_IMG 8
#define NBLK         (BATCH * BLKS_PER_IMG)   // 512
#define TPB          256
#define NPATCH       (127 * 127)              // 16129

// per-block partial monomial sums:
// [0]: Sca0, Sca1, Scc, Sss   [1]: La0, La1, La2, La3
__device__ float4       g_part[NBLK][2];
__device__ unsigned int g_cnt[BATCH];   // zero-init; finisher resets

__global__ void __launch_bounds__(TPB) fused_kernel(
    const float* __restrict__ x,
    const float* __restrict__ conv_w,
    const float* __restrict__ conv_b,
    const float* __restrict__ ry,      // (2,4)
    const float* __restrict__ head_w,  // (1,2)
    const float* __restrict__ head_b,
    float* __restrict__ out)
{
    __shared__ float sh[8][8];
    __shared__ bool  s_fin;

    const int tid  = threadIdx.x;
    const int wid  = tid >> 5;
    const int lane = tid & 31;
    const int b    = blockIdx.x >> 3;        // image
    const int q    = blockIdx.x & 7;         // 16-row group

    // Prefetch params into registers (warp 0) — ready long before finalize.
    float pr[8], pw[4], pcb, ph0, ph1, phb;
    if (wid == 0) {
        #pragma unroll
        for (int i = 0; i < 8; i++) pr[i] = ry[i];
        #pragma unroll
        for (int i = 0; i < 4; i++) pw[i] = conv_w[i];
        pcb = conv_b[0]; ph0 = head_w[0]; ph1 = head_w[1]; phb = head_b[0];
    }

    const float* __restrict__ img = x + (size_t)b * 16384;
    const int r0 = q * 16 + wid;        // first row
    const int r1 = r0 + 8;              // second row

    // ---- front-batched loads: each pixel read exactly once ----
    const float4 v0 = *(const float4*)(img + r0 * 128 + lane * 4);
    const float4 v1 = *(const float4*)(img + r1 * 128 + lane * 4);

    float S0 = 0.f, S1 = 0.f, S2 = 0.f, S3 = 0.f;
    float S4 = 0.f, S5 = 0.f, S6 = 0.f, S7 = 0.f;

    const bool l31 = (lane == 31);
    const bool l0  = (lane == 0);

    #pragma unroll
    for (int it = 0; it < 2; it++) {
        const float4 v  = it ? v1 : v0;
        const int   row = it ? r1 : r0;

        const float rs = (v.x + v.y) + (v.z + v.w);
        const float e0 = l0  ? v.x : 0.f;   // col 0
        const float e3 = l31 ? v.w : 0.f;   // col 127

        if (row < 127) {                    // warp-uniform
            // linear sums over rows 0..126
            S4 += rs - e3;                  // La0: cols 0..126
            S5 += rs - e0;                  // La1: cols 1..127
            // trig sums (only rows 0..126 ever need trig)
            float ca0, sa0, ca1, sa1, ca2, sa2, ca3, sa3;
            __sincosf(v.x, &sa0, &ca0);
            __sincosf(v.y, &sa1, &ca1);
            __sincosf(v.z, &sa2, &ca2);
            __sincosf(v.w, &sa3, &ca3);
            const float ca4 = __shfl_down_sync(0xFFFFFFFFu, ca0, 1);
            const float sa4 = __shfl_down_sync(0xFFFFFFFFu, sa0, 1);

            const float tc = (ca0 + ca1) + (ca2 + ca3);
            S0 += tc - (l31 ? ca3 : 0.f);   // Sca0: cols 0..126
            S1 += tc - (l0  ? ca0 : 0.f);   // Sca1: cols 1..127
            S2 += ca0 * ca1 + ca1 * ca2 + ca2 * ca3 + (l31 ? 0.f : ca3 * ca4);
            S3 += sa0 * sa1 + sa1 * sa2 + sa2 * sa3 + (l31 ? 0.f : sa3 * sa4);
        }
        if (row > 0) {                      // warp-uniform
            // linear sums over rows 1..127
            S6 += rs - e3;                  // La2: cols 0..126
            S7 += rs - e0;                  // La3: cols 1..127
        }
    }

    // warp tree reduction (deterministic)
    #pragma unroll
    for (int off = 16; off > 0; off >>= 1) {
        const unsigned m = 0xFFFFFFFFu;
        S0 += __shfl_down_sync(m, S0, off);
        S1 += __shfl_down_sync(m, S1, off);
        S2 += __shfl_down_sync(m, S2, off);
        S3 += __shfl_down_sync(m, S3, off);
        S4 += __shfl_down_sync(m, S4, off);
        S5 += __shfl_down_sync(m, S5, off);
        S6 += __shfl_down_sync(m, S6, off);
        S7 += __shfl_down_sync(m, S7, off);
    }
    if (lane == 0) {
        sh[wid][0] = S0; sh[wid][1] = S1; sh[wid][2] = S2; sh[wid][3] = S3;
        sh[wid][4] = S4; sh[wid][5] = S5; sh[wid][6] = S6; sh[wid][7] = S7;
    }
    __syncthreads();

    if (tid < 8) {   // fixed-order cross-warp reduce
        float v = sh[0][tid];
        #pragma unroll
        for (int w = 1; w < 8; w++) v += sh[w][tid];
        sh[0][tid] = v;
    }
    __syncthreads();

    if (tid == 0) {
        g_part[blockIdx.x][0] = make_float4(sh[0][0], sh[0][1], sh[0][2], sh[0][3]);
        g_part[blockIdx.x][1] = make_float4(sh[0][4], sh[0][5], sh[0][6], sh[0][7]);
        __threadfence();
        unsigned done = atomicAdd(&g_cnt[b], 1u);
        s_fin = (done == BLKS_PER_IMG - 1);
    }
    __syncthreads();

    // ---- per-image finisher: last block of this image ----
    if (s_fin && tid == 0) {
        __threadfence();
        float m0 = 0.f, m1 = 0.f, m2 = 0.f, m3 = 0.f;
        float m4 = 0.f, m5 = 0.f, m6 = 0.f, m7 = 0.f;
        #pragma unroll
        for (int k = 0; k < BLKS_PER_IMG; k++) {
            const float4 pa = __ldcg(&g_part[b * BLKS_PER_IMG + k][0]);
            const float4 pc = __ldcg(&g_part[b * BLKS_PER_IMG + k][1]);
            m0 += pa.x; m1 += pa.y; m2 += pa.z; m3 += pa.w;
            m4 += pc.x; m5 += pc.y; m6 += pc.z; m7 += pc.w;
        }

        // coefficients from register-resident params
        float U[4][4] = {{1,0,0,0},{0,1,0,0},{0,0,1,0},{0,0,0,1}};
        #pragma unroll
        for (int l = 0; l < 2; l++) {
            float c0, s0, c1, s1;
            __sincosf(0.5f * pr[l * 4 + 0], &s0, &c0);
            __sincosf(0.5f * pr[l * 4 + 1], &s1, &c1);
            float A2[2][2] = {{c0, -s0}, {s0, c0}};
            float B2[2][2] = {{c1, -s1}, {s1, c1}};
            float T[4][4];
            #pragma unroll
            for (int i = 0; i < 4; i++)
                #pragma unroll
                for (int j = 0; j < 4; j++) {
                    float s = 0.f;
                    #pragma unroll
                    for (int kx = 0; kx < 4; kx++)
                        s += A2[i >> 1][kx >> 1] * B2[i & 1][kx & 1] * U[kx][j];
                    T[i][j] = s;
                }
            #pragma unroll
            for (int j = 0; j < 4; j++) {
                U[0][j] = T[0][j]; U[1][j] = T[1][j];
                U[2][j] = T[3][j]; U[3][j] = T[2][j];
            }
        }
        float M00 = 0, M03 = 0, M33 = 0, M11 = 0, M12 = 0, M22 = 0;
        #pragma unroll
        for (int i = 0; i < 4; i++) {
            float z = (i < 2) ? 1.0f : -1.0f;
            M00 += z * U[i][0] * U[i][0];
            M03 += z * U[i][0] * U[i][3];
            M33 += z * U[i][3] * U[i][3];
            M11 += z * U[i][1] * U[i][1];
            M12 += z * U[i][1] * U[i][2];
            M22 += z * U[i][2] * U[i][2];
        }
        const float c_q0 = ph1 * M00;
        const float c_q1 = ph1 * (-2.0f * M03);
        const float c_q2 = ph1 * M33;
        const float c_q3 = ph1 * M11;
        const float c_q4 = ph1 * (2.0f * M12);
        const float c_q5 = ph1 * M22;
        const float A  = 0.25f * (c_q0 + c_q2 + c_q3 + c_q5);
        const float Bc = 0.25f * (c_q0 - c_q2 + c_q3 - c_q5);
        const float Cc = 0.25f * (c_q0 - c_q2 - c_q3 + c_q5);
        const float Dc = 0.25f * (c_q0 + c_q2 - c_q3 - c_q5);
        const float Ec = 0.25f * (c_q1 + c_q4);

        const float qsum = A * (float)NPATCH + Bc * m0 + Cc * m1 + Dc * m2 + Ec * m3;
        const float csum = ph0 * (pw[0] * m4 + pw[1] * m5 + pw[2] * m6 + pw[3] * m7);
        out[b] = (qsum + csum) * (1.0f / (float)NPATCH) + ph0 * pcb + phb;

        g_cnt[b] = 0;   // reset for next graph replay
    }
}

extern "C" void kernel_launch(void* const* d_in, const int* in_sizes, int n_in,
                              void* d_out, int out_size) {
    const float* x      = (const float*)d_in[0];
    const float* conv_w = (const float*)d_in[1];
    const float* conv_b = (const float*)d_in[2];
    const float* ry     = (const float*)d_in[3];
    const float* head_w = (const float*)d_in[4];
    const float* head_b = (const float*)d_in[5];
    float* out = (float*)d_out;

    fused_kernel<<<NBLK, TPB>>>(x, conv_w, conv_b, ry, head_w, head_b, out);
}

// round 6
// speedup vs baseline: 1.3241x; 1.0711x over previous
#include <cuda_runtime.h>

#define BATCH   64
#define TPB     1024
#define NPATCH  (127 * 127)   // 16129

// One block per image. No inter-block communication, no device scratch state.
__global__ void __launch_bounds__(TPB, 1) fused_kernel(
    const float* __restrict__ x,
    const float* __restrict__ conv_w,
    const float* __restrict__ conv_b,
    const float* __restrict__ ry,      // (2,4)
    const float* __restrict__ head_w,  // (1,2)
    const float* __restrict__ head_b,
    float* __restrict__ out)
{
    __shared__ float sh[32][9];   // [warp][monomial], padded: conflict-free
    __shared__ float tot[8];

    const int tid  = threadIdx.x;
    const int wid  = tid >> 5;
    const int lane = tid & 31;
    const int b    = blockIdx.x;

    // Thread 0 prefetches params into registers; used only in the final step,
    // loads fully overlap the main phase.
    float pr[8], pwt[4], pcb, ph0, ph1, phb;
    if (tid == 0) {
        #pragma unroll
        for (int i = 0; i < 8; i++) pr[i] = ry[i];
        #pragma unroll
        for (int i = 0; i < 4; i++) pwt[i] = conv_w[i];
        pcb = conv_b[0]; ph0 = head_w[0]; ph1 = head_w[1]; phb = head_b[0];
    }

    // ---- front-batched loads: warp owns rows 4w..4w+3, lane owns 4 cols ----
    const float* __restrict__ p = x + (size_t)b * 16384 + wid * 4 * 128 + lane * 4;
    float4 v[4];
    #pragma unroll
    for (int i = 0; i < 4; i++) v[i] = *(const float4*)(p + i * 128);

    float S0 = 0.f, S1 = 0.f, S2 = 0.f, S3 = 0.f;   // Sca0, Sca1, Scc, Sss
    float S4 = 0.f, S5 = 0.f, S6 = 0.f, S7 = 0.f;   // La0, La1, La2, La3

    const bool l31 = (lane == 31);
    const bool l0  = (lane == 0);

    #pragma unroll
    for (int i = 0; i < 4; i++) {
        const int   row = wid * 4 + i;     // warp-uniform
        const float4 vv = v[i];

        const float rs = (vv.x + vv.y) + (vv.z + vv.w);
        const float e0 = l0  ? vv.x : 0.f;   // col 0
        const float e3 = l31 ? vv.w : 0.f;   // col 127

        if (row < 127) {
            S4 += rs - e3;                   // La0: rows 0..126, cols 0..126
            S5 += rs - e0;                   // La1: rows 0..126, cols 1..127

            float ca0, sa0, ca1, sa1, ca2, sa2, ca3, sa3;
            __sincosf(vv.x, &sa0, &ca0);
            __sincosf(vv.y, &sa1, &ca1);
            __sincosf(vv.z, &sa2, &ca2);
            __sincosf(vv.w, &sa3, &ca3);
            const float ca4 = __shfl_down_sync(0xFFFFFFFFu, ca0, 1);
            const float sa4 = __shfl_down_sync(0xFFFFFFFFu, sa0, 1);

            const float tc = (ca0 + ca1) + (ca2 + ca3);
            S0 += tc - (l31 ? ca3 : 0.f);    // Sca0: cols 0..126
            S1 += tc - (l0  ? ca0 : 0.f);    // Sca1: cols 1..127
            S2 += ca0 * ca1 + ca1 * ca2 + ca2 * ca3 + (l31 ? 0.f : ca3 * ca4);
            S3 += sa0 * sa1 + sa1 * sa2 + sa2 * sa3 + (l31 ? 0.f : sa3 * sa4);
        }
        if (row > 0) {
            S6 += rs - e3;                   // La2: rows 1..127, cols 0..126
            S7 += rs - e0;                   // La3: rows 1..127, cols 1..127
        }
    }

    // ---- warp tree reduction (deterministic) ----
    #pragma unroll
    for (int off = 16; off > 0; off >>= 1) {
        const unsigned m = 0xFFFFFFFFu;
        S0 += __shfl_down_sync(m, S0, off);
        S1 += __shfl_down_sync(m, S1, off);
        S2 += __shfl_down_sync(m, S2, off);
        S3 += __shfl_down_sync(m, S3, off);
        S4 += __shfl_down_sync(m, S4, off);
        S5 += __shfl_down_sync(m, S5, off);
        S6 += __shfl_down_sync(m, S6, off);
        S7 += __shfl_down_sync(m, S7, off);
    }
    if (lane == 0) {
        sh[wid][0] = S0; sh[wid][1] = S1; sh[wid][2] = S2; sh[wid][3] = S3;
        sh[wid][4] = S4; sh[wid][5] = S5; sh[wid][6] = S6; sh[wid][7] = S7;
    }
    __syncthreads();

    // ---- cross-warp: warp w (<8) reduces monomial w over 32 warps ----
    if (wid < 8) {
        float vv = sh[lane][wid];
        #pragma unroll
        for (int off = 16; off > 0; off >>= 1)
            vv += __shfl_down_sync(0xFFFFFFFFu, vv, off);
        if (lane == 0) tot[wid] = vv;
    }
    __syncthreads();

    // ---- thread 0: coefficients (register params) + final output ----
    if (tid == 0) {
        const float m0 = tot[0], m1 = tot[1], m2 = tot[2], m3 = tot[3];
        const float m4 = tot[4], m5 = tot[5], m6 = tot[6], m7 = tot[7];

        float U[4][4] = {{1,0,0,0},{0,1,0,0},{0,0,1,0},{0,0,0,1}};
        #pragma unroll
        for (int l = 0; l < 2; l++) {
            float c0, s0, c1, s1;
            __sincosf(0.5f * pr[l * 4 + 0], &s0, &c0);
            __sincosf(0.5f * pr[l * 4 + 1], &s1, &c1);
            float A2[2][2] = {{c0, -s0}, {s0, c0}};
            float B2[2][2] = {{c1, -s1}, {s1, c1}};
            float T[4][4];
            #pragma unroll
            for (int i = 0; i < 4; i++)
                #pragma unroll
                for (int j = 0; j < 4; j++) {
                    float s = 0.f;
                    #pragma unroll
                    for (int kx = 0; kx < 4; kx++)
                        s += A2[i >> 1][kx >> 1] * B2[i & 1][kx & 1] * U[kx][j];
                    T[i][j] = s;
                }
            #pragma unroll
            for (int j = 0; j < 4; j++) {
                U[0][j] = T[0][j]; U[1][j] = T[1][j];
                U[2][j] = T[3][j]; U[3][j] = T[2][j];
            }
        }
        float M00 = 0, M03 = 0, M33 = 0, M11 = 0, M12 = 0, M22 = 0;
        #pragma unroll
        for (int i = 0; i < 4; i++) {
            float z = (i < 2) ? 1.0f : -1.0f;
            M00 += z * U[i][0] * U[i][0];
            M03 += z * U[i][0] * U[i][3];
            M33 += z * U[i][3] * U[i][3];
            M11 += z * U[i][1] * U[i][1];
            M12 += z * U[i][1] * U[i][2];
            M22 += z * U[i][2] * U[i][2];
        }
        const float c_q0 = ph1 * M00;
        const float c_q1 = ph1 * (-2.0f * M03);
        const float c_q2 = ph1 * M33;
        const float c_q3 = ph1 * M11;
        const float c_q4 = ph1 * (2.0f * M12);
        const float c_q5 = ph1 * M22;
        const float A  = 0.25f * (c_q0 + c_q2 + c_q3 + c_q5);
        const float Bc = 0.25f * (c_q0 - c_q2 + c_q3 - c_q5);
        const float Cc = 0.25f * (c_q0 - c_q2 - c_q3 + c_q5);
        const float Dc = 0.25f * (c_q0 + c_q2 - c_q3 - c_q5);
        const float Ec = 0.25f * (c_q1 + c_q4);

        const float qsum = A * (float)NPATCH + Bc * m0 + Cc * m1 + Dc * m2 + Ec * m3;
        const float csum = ph0 * (pwt[0] * m4 + pwt[1] * m5 + pwt[2] * m6 + pwt[3] * m7);
        out[b] = (qsum + csum) * (1.0f / (float)NPATCH) + ph0 * pcb + phb;
    }
}

extern "C" void kernel_launch(void* const* d_in, const int* in_sizes, int n_in,
                              void* d_out, int out_size) {
    const float* x      = (const float*)d_in[0];
    const float* conv_w = (const float*)d_in[1];
    const float* conv_b = (const float*)d_in[2];
    const float* ry     = (const float*)d_in[3];
    const float* head_w = (const float*)d_in[4];
    const float* head_b = (const float*)d_in[5];
    float* out = (float*)d_out;

    fused_kernel<<<BATCH, TPB>>>(x, conv_w, conv_b, ry, head_w, head_b, out);
}